// round 15
// baseline (speedup 1.0000x reference)
#include <cuda_runtime.h>
#include <cuda_bf16.h>

// out[n, d] = dist[n] * w[d]   (N = 1,000,000 rows, DIM = 256, fp32)
// R13: R5 champion structure (x8 unroll, grid-stride, __stcs streaming
// stores, 64-bit indices, regs=40) with ONE change: grid sized to exactly
// one resident wave at the measured occupancy (6 CTAs/SM at 40 regs):
// NBLK = 148 * 6 = 888. Eliminates the ragged 296-CTA second wave that the
// 1184-CTA launch had at 6 CTAs/SM. Stride 888*256 = 227328 is a multiple
// of 64, so each thread still owns a fixed column (weight in registers)
// and dist loads stay warp-uniform.

#define DIM 256
#define VEC4_PER_ROW (DIM / 4)   // 64
#define TPB 256
#define NBLK 888                 // 148 SMs * 6 resident CTAs (regs=40) -> 1 wave
#define UNROLL 8

__global__ __launch_bounds__(TPB) void outer_product_persistent(
    const float* __restrict__ dist,
    const float* __restrict__ weight,
    float4* __restrict__ out,
    int n_rows)
{
    const int col4 = threadIdx.x & (VEC4_PER_ROW - 1);
    const float4 w = __ldg(&reinterpret_cast<const float4*>(weight)[col4]);

    const long long stride = (long long)gridDim.x * TPB;        // 227328, mult of 64
    const long long total  = (long long)n_rows * VEC4_PER_ROW;  // 64M vec4
    long long i = (long long)blockIdx.x * TPB + threadIdx.x;

    // Main loop: 8 rows per iteration. Front-batch the (warp-uniform) dist
    // loads, then compute+store each element immediately so register live
    // ranges stay short.
    for (; i + (UNROLL - 1) * stride < total; i += (long long)UNROLL * stride) {
        float d[UNROLL];
#pragma unroll
        for (int j = 0; j < UNROLL; j++) {
            d[j] = __ldg(&dist[(int)((i + j * stride) >> 6)]);
        }
#pragma unroll
        for (int j = 0; j < UNROLL; j++) {
            float4 r;
            r.x = d[j] * w.x;
            r.y = d[j] * w.y;
            r.z = d[j] * w.z;
            r.w = d[j] * w.w;
            __stcs(&out[i + j * stride], r);   // evict-first streaming store
        }
    }

    // Tail.
    for (; i < total; i += stride) {
        const float dd = __ldg(&dist[(int)(i >> 6)]);
        float4 r;
        r.x = dd * w.x; r.y = dd * w.y; r.z = dd * w.z; r.w = dd * w.w;
        __stcs(&out[i], r);
    }
}

extern "C" void kernel_launch(void* const* d_in, const int* in_sizes, int n_in,
                              void* d_out, int out_size)
{
    const float* dist   = (const float*)d_in[0];
    const float* weight = (const float*)d_in[1];
    float4* out         = (float4*)d_out;

    int n_rows = in_sizes[0];   // 1,000,000

    outer_product_persistent<<<NBLK, TPB>>>(dist, weight, out, n_rows);
}

// round 16
// speedup vs baseline: 1.0656x; 1.0656x over previous
#include <cuda_runtime.h>
#include <cuda_bf16.h>

// out[n, d] = dist[n] * w[d]   (N = 1,000,000 rows, DIM = 256, fp32)
// R15: champion R5 structure (grid-stride interleave over 1184 CTAs,
// __stcs streaming STG.128, 64-bit indices, fixed column per thread)
// with UNROLL doubled 8 -> 16: deeper per-warp store bursts to feed the
// L2->DRAM write stream across dist-load latency gaps; halved loop
// overhead. Occupancy drops (regs up), but aggregate outstanding stores
// per SM increase.

#define DIM 256
#define VEC4_PER_ROW (DIM / 4)   // 64
#define TPB 256
#define NBLK 1184                // 148 SMs; back-fill scheduling as CTAs drain
#define UNROLL 16

__global__ __launch_bounds__(TPB) void outer_product_persistent(
    const float* __restrict__ dist,
    const float* __restrict__ weight,
    float4* __restrict__ out,
    int n_rows)
{
    const int col4 = threadIdx.x & (VEC4_PER_ROW - 1);
    const float4 w = __ldg(&reinterpret_cast<const float4*>(weight)[col4]);

    const long long stride = (long long)gridDim.x * TPB;        // multiple of 64
    const long long total  = (long long)n_rows * VEC4_PER_ROW;  // 64M vec4
    long long i = (long long)blockIdx.x * TPB + threadIdx.x;

    // Main loop: 16 rows per iteration. Front-batch the (warp-uniform)
    // dist loads, then compute+store each element immediately so register
    // live ranges stay short.
    for (; i + (UNROLL - 1) * stride < total; i += (long long)UNROLL * stride) {
        float d[UNROLL];
#pragma unroll
        for (int j = 0; j < UNROLL; j++) {
            d[j] = __ldg(&dist[(int)((i + j * stride) >> 6)]);
        }
#pragma unroll
        for (int j = 0; j < UNROLL; j++) {
            float4 r;
            r.x = d[j] * w.x;
            r.y = d[j] * w.y;
            r.z = d[j] * w.z;
            r.w = d[j] * w.w;
            __stcs(&out[i + j * stride], r);   // evict-first streaming store
        }
    }

    // Tail.
    for (; i < total; i += stride) {
        const float dd = __ldg(&dist[(int)(i >> 6)]);
        float4 r;
        r.x = dd * w.x; r.y = dd * w.y; r.z = dd * w.z; r.w = dd * w.w;
        __stcs(&out[i], r);
    }
}

extern "C" void kernel_launch(void* const* d_in, const int* in_sizes, int n_in,
                              void* d_out, int out_size)
{
    const float* dist   = (const float*)d_in[0];
    const float* weight = (const float*)d_in[1];
    float4* out         = (float4*)d_out;

    int n_rows = in_sizes[0];   // 1,000,000

    outer_product_persistent<<<NBLK, TPB>>>(dist, weight, out, n_rows);
}